// round 2
// baseline (speedup 1.0000x reference)
#include <cuda_runtime.h>

// Problem constants
#define N_ 32
#define D_ 128
#define S_ 128
#define M_ 64
#define MM_ (M_*M_)

// ---------------- scratch (__device__ globals; no allocations allowed) ----------------
__device__ float g_mc[N_*D_*M_];   // mean over i of x[n,d,i,v]  (indexed by v)
__device__ float g_dg[N_*D_*M_];   // diag
__device__ float g_md[N_*D_];      // mean of diag
__device__ float g_ma[N_*D_];      // mean of all
__device__ float g_c2[D_*S_];      // coeffs[:, :, 1], layout [d][s]
__device__ float g_c13[D_*S_*2];   // (0.5*c1, 0.5*c3) interleaved, layout [d][s][2]
__device__ float g_c45[D_*S_*2];   // (c4, c5) interleaved
__device__ float g_P[N_*S_*M_];    // P[n,s,v]
__device__ float g_Q[N_*S_];       // Q[n,s] (includes bias)

// ---------------- kernel 0: split coeffs into GEMM-friendly layouts ----------------
__global__ void prep_coeffs_kernel(const float* __restrict__ coeffs) {
    int idx = blockIdx.x * blockDim.x + threadIdx.x;   // idx = d*S + s
    if (idx < D_*S_) {
        const float* c = coeffs + idx * 5;
        g_c2[idx]        = c[1];
        g_c13[idx*2]     = 0.5f * c[0];
        g_c13[idx*2 + 1] = 0.5f * c[2];
        g_c45[idx*2]     = c[3];
        g_c45[idx*2 + 1] = c[4];
    }
}

// ---------------- kernel 1: per-(n,d) stats over the 64x64 tile ----------------
// block = one (n,d); 64 threads, thread = column v. Row-wise loads are coalesced
// (lanes 0..31 read 128B contiguous).
__global__ __launch_bounds__(64) void stats_kernel(const float* __restrict__ x) {
    int nd = blockIdx.x;            // n*D + d
    int v  = threadIdx.x;           // 0..63
    const float* p = x + (size_t)nd * MM_;

    float s0 = 0.f, s1 = 0.f, s2 = 0.f, s3 = 0.f;
    #pragma unroll
    for (int i = 0; i < M_; i += 4) {
        s0 += p[(i+0)*M_ + v];
        s1 += p[(i+1)*M_ + v];
        s2 += p[(i+2)*M_ + v];
        s3 += p[(i+3)*M_ + v];
    }
    float colsum = (s0 + s1) + (s2 + s3);
    g_mc[nd*M_ + v] = colsum * (1.0f / M_);

    float dg = p[v*M_ + v];
    g_dg[nd*M_ + v] = dg;

    // reduce colsum and diag across 64 threads (2 warps)
    float c = colsum, d = dg;
    #pragma unroll
    for (int off = 16; off > 0; off >>= 1) {
        c += __shfl_xor_sync(0xffffffffu, c, off);
        d += __shfl_xor_sync(0xffffffffu, d, off);
    }
    __shared__ float sc[2], sd[2];
    if ((v & 31) == 0) { sc[v >> 5] = c; sd[v >> 5] = d; }
    __syncthreads();
    if (v == 0) {
        g_ma[nd] = (sc[0] + sc[1]) * (1.0f / MM_);
        g_md[nd] = (sd[0] + sd[1]) * (1.0f / M_);
    }
}

// ---------------- kernel 2: P[n,s,v] and Q[n,s] ----------------
// grid (S/8, N); 64 threads; thread = v; 8 s-values per block.
__global__ __launch_bounds__(64) void pq_kernel(const float* __restrict__ bias) {
    int n  = blockIdx.y;
    int s0 = blockIdx.x * 8;
    int v  = threadIdx.x;

    __shared__ float2 c13s[D_][8];     // (0.5*c1, 0.5*c3) for this s-tile: 4KB
    const float2* c13g = (const float2*)g_c13;
    for (int idx = v; idx < D_ * 8; idx += 64) {
        int d = idx >> 3, t = idx & 7;
        c13s[d][t] = c13g[d*S_ + s0 + t];
    }
    __syncthreads();

    float acc[8] = {0.f, 0.f, 0.f, 0.f, 0.f, 0.f, 0.f, 0.f};
    int base = n * D_;
    for (int d = 0; d < D_; d++) {
        float mcv = g_mc[(base + d)*M_ + v];
        float dgv = g_dg[(base + d)*M_ + v];
        #pragma unroll
        for (int t = 0; t < 8; t++) {
            float2 c = c13s[d][t];
            acc[t] += c.x * mcv + c.y * dgv;
        }
    }
    #pragma unroll
    for (int t = 0; t < 8; t++)
        g_P[(n*S_ + s0 + t)*M_ + v] = acc[t];

    if (v < 8) {
        int s = s0 + v;
        const float2* c45g = (const float2*)g_c45;
        float q = 0.f;
        for (int d = 0; d < D_; d++) {
            float2 c = c45g[d*S_ + s];
            q += c.x * g_md[base + d] + c.y * g_ma[base + d];
        }
        g_Q[n*S_ + s] = q + bias[s];
    }
}

// ---------------- kernel 3: main batched SGEMM + epilogue ----------------
// out[n,s,i,:] for all s: block = (i, n). Tile [BM=128 s] x [BN=64 j], K=D=128, BK=8.
// 256 threads: thread (ty,tx) computes TM=8 s x TN=4 j. Double-buffered smem.
#define BK 8
__global__ __launch_bounds__(256) void gemm_kernel(const float* __restrict__ x,
                                                   float* __restrict__ out) {
    int i   = blockIdx.x;          // row 0..63
    int n   = blockIdx.y;          // batch
    int tid = threadIdx.x;
    int tx  = tid & 15;            // j = tx*4 .. tx*4+3
    int ty  = tid >> 4;            // s = ty*8 .. ty*8+7

    __shared__ float As[2][BK][S_];   // 8KB
    __shared__ float Bs[2][BK][M_];   // 4KB

    const float* xb = x + (size_t)(n * D_) * MM_ + i * M_;  // + d*MM_ + j

    // cooperative load indices
    int ar = tid >> 5;             // 0..7
    int ac = (tid & 31) * 4;       // 0..124
    int br = tid >> 4;             // 0..15 (only tid<128 used)
    int bc = (tid & 15) * 4;       // 0..60

    // preload tile 0
    float4 pa = *(const float4*)&g_c2[ar * S_ + ac];
    float4 pb;
    if (tid < 128) pb = *(const float4*)&xb[(size_t)br * MM_ + bc];
    *(float4*)&As[0][ar][ac] = pa;
    if (tid < 128) *(float4*)&Bs[0][br][bc] = pb;
    __syncthreads();

    float acc[8][4];
    #pragma unroll
    for (int m = 0; m < 8; m++)
        #pragma unroll
        for (int v = 0; v < 4; v++) acc[m][v] = 0.f;

    int buf = 0;
    #pragma unroll 1
    for (int kt = 0; kt < D_ / BK; kt++) {
        int k0n = (kt + 1) * BK;
        if (kt + 1 < D_ / BK) {
            pa = *(const float4*)&g_c2[(k0n + ar) * S_ + ac];
            if (tid < 128) pb = *(const float4*)&xb[(size_t)(k0n + br) * MM_ + bc];
        }
        #pragma unroll
        for (int kk = 0; kk < BK; kk++) {
            float a[8], b[4];
            *(float4*)&a[0] = *(const float4*)&As[buf][kk][ty*8];
            *(float4*)&a[4] = *(const float4*)&As[buf][kk][ty*8 + 4];
            *(float4*)&b[0] = *(const float4*)&Bs[buf][kk][tx*4];
            #pragma unroll
            for (int m = 0; m < 8; m++)
                #pragma unroll
                for (int v = 0; v < 4; v++)
                    acc[m][v] += a[m] * b[v];
        }
        if (kt + 1 < D_ / BK) {
            buf ^= 1;
            *(float4*)&As[buf][ar][ac] = pa;
            if (tid < 128) *(float4*)&Bs[buf][br][bc] = pb;
        }
        __syncthreads();
    }

    // epilogue: + P[n,s,i] + P[n,s,j] + Q[n,s]
    int sbase = ty * 8;
    #pragma unroll
    for (int m = 0; m < 8; m++) {
        int s = sbase + m;
        const float* Pn = &g_P[(n*S_ + s) * M_];
        float  pi = Pn[i];
        float  q  = g_Q[n*S_ + s];
        float4 pj = *(const float4*)&Pn[tx*4];
        float4 r;
        r.x = acc[m][0] + pi + pj.x + q;
        r.y = acc[m][1] + pi + pj.y + q;
        r.z = acc[m][2] + pi + pj.z + q;
        r.w = acc[m][3] + pi + pj.w + q;
        *(float4*)&out[((size_t)(n*S_ + s)) * MM_ + i * M_ + tx*4] = r;
    }
}

// ---------------- launch ----------------
extern "C" void kernel_launch(void* const* d_in, const int* in_sizes, int n_in,
                              void* d_out, int out_size) {
    const float* x      = (const float*)d_in[0];   // [N,D,M,M]
    const float* coeffs = (const float*)d_in[1];   // [D,S,5]
    const float* bias   = (const float*)d_in[2];   // [1,S,1,1]
    float* out = (float*)d_out;                    // [N,S,M,M]

    prep_coeffs_kernel<<<64, 256>>>(coeffs);
    stats_kernel<<<N_ * D_, 64>>>(x);
    pq_kernel<<<dim3(S_ / 8, N_), 64>>>(bias);
    gemm_kernel<<<dim3(M_, N_), 256>>>(x, out);
}

// round 3
// speedup vs baseline: 1.4175x; 1.4175x over previous
#include <cuda_runtime.h>
#include <cstdint>

// Problem constants
#define N_ 32
#define D_ 128
#define S_ 128
#define M_ 64
#define MM_ (M_*M_)

// ---------------- scratch (__device__ globals; no allocations allowed) ----------------
__device__ float g_mc[N_*D_*M_];   // mean over i of x[n,d,i,v]
__device__ float g_dg[N_*D_*M_];   // diag
__device__ float g_md[N_*D_];      // mean of diag
__device__ float g_ma[N_*D_];      // mean of all
__device__ float g_c2[D_*S_];      // coeffs[:,:,1], tf32-rounded, layout [d][s]
__device__ float g_c13[D_*S_*2];   // (0.5*c1, 0.5*c3) interleaved, layout [d][s][2]
__device__ float g_c45[D_*S_*2];   // (c4, c5) interleaved
__device__ float g_P[N_*S_*M_];    // P[n,s,v]
__device__ float g_Q[N_*S_];       // Q[n,s] (includes bias)

__device__ __forceinline__ float tf32r(float x) {
    uint32_t r;
    asm("cvt.rna.tf32.f32 %0, %1;" : "=r"(r) : "f"(x));
    return __uint_as_float(r);
}

// ---------------- kernel 0: split coeffs ----------------
__global__ void prep_coeffs_kernel(const float* __restrict__ coeffs) {
    int idx = blockIdx.x * blockDim.x + threadIdx.x;   // idx = d*S + s
    if (idx < D_*S_) {
        const float* c = coeffs + idx * 5;
        g_c2[idx]        = tf32r(c[1]);      // pre-rounded for tensor-core GEMM
        g_c13[idx*2]     = 0.5f * c[0];
        g_c13[idx*2 + 1] = 0.5f * c[2];
        g_c45[idx*2]     = c[3];
        g_c45[idx*2 + 1] = c[4];
    }
}

// ---------------- kernel 1: per-(n,d) stats, float4 loads, MLP=8 ----------------
__global__ __launch_bounds__(128) void stats_kernel(const float* __restrict__ x) {
    int nd = blockIdx.x;
    const float* p = x + (size_t)nd * MM_;
    int t = threadIdx.x;
    int q = t & 15;          // float4 column group (covers 64 floats)
    int r = t >> 4;          // 0..7

    float4 acc = make_float4(0.f, 0.f, 0.f, 0.f);
    #pragma unroll
    for (int i = 0; i < 8; i++) {
        float4 v = *(const float4*)&p[(i*8 + r)*M_ + q*4];
        acc.x += v.x; acc.y += v.y; acc.z += v.z; acc.w += v.w;
    }

    __shared__ float4 part[128];
    __shared__ float  red[16], red2[16];
    part[t] = acc;
    float dval = 0.f;
    if (t < M_) {
        dval = p[t*M_ + t];
        g_dg[nd*M_ + t] = dval;
    }
    __syncthreads();

    if (t < 16) {
        float4 cs = part[t];
        #pragma unroll
        for (int rr = 1; rr < 8; rr++) {
            float4 v = part[rr*16 + t];
            cs.x += v.x; cs.y += v.y; cs.z += v.z; cs.w += v.w;
        }
        float4 mc;
        mc.x = cs.x * (1.0f/M_); mc.y = cs.y * (1.0f/M_);
        mc.z = cs.z * (1.0f/M_); mc.w = cs.w * (1.0f/M_);
        *(float4*)&g_mc[nd*M_ + t*4] = mc;
        red[t] = cs.x + cs.y + cs.z + cs.w;
    }
    __shared__ float diags[64];
    if (t < 64) diags[t] = dval;
    __syncthreads();
    if (t < 16) red2[t] = diags[t] + diags[t+16] + diags[t+32] + diags[t+48];
    __syncthreads();
    if (t == 0) {
        float sa = 0.f, sd = 0.f;
        #pragma unroll
        for (int k = 0; k < 16; k++) { sa += red[k]; sd += red2[k]; }
        g_ma[nd] = sa * (1.0f/MM_);
        g_md[nd] = sd * (1.0f/M_);
    }
}

// ---------------- kernel 2: P[n,s,v] and Q[n,s] ----------------
__global__ __launch_bounds__(64) void pq_kernel(const float* __restrict__ bias) {
    int n  = blockIdx.y;
    int s0 = blockIdx.x * 8;
    int v  = threadIdx.x;

    __shared__ float2 c13s[D_][8];
    const float2* c13g = (const float2*)g_c13;
    for (int idx = v; idx < D_ * 8; idx += 64) {
        int d = idx >> 3, t = idx & 7;
        c13s[d][t] = c13g[d*S_ + s0 + t];
    }
    __syncthreads();

    float acc[8] = {0.f,0.f,0.f,0.f,0.f,0.f,0.f,0.f};
    int base = n * D_;
    for (int d = 0; d < D_; d++) {
        float mcv = g_mc[(base + d)*M_ + v];
        float dgv = g_dg[(base + d)*M_ + v];
        #pragma unroll
        for (int t = 0; t < 8; t++) {
            float2 c = c13s[d][t];
            acc[t] += c.x * mcv + c.y * dgv;
        }
    }
    #pragma unroll
    for (int t = 0; t < 8; t++)
        g_P[(n*S_ + s0 + t)*M_ + v] = acc[t];

    if (v < 8) {
        int s = s0 + v;
        const float2* c45g = (const float2*)g_c45;
        float q = 0.f;
        for (int d = 0; d < D_; d++) {
            float2 c = c45g[d*S_ + s];
            q += c.x * g_md[base + d] + c.y * g_ma[base + d];
        }
        g_Q[n*S_ + s] = q + bias[s];
    }
}

// ---------------- kernel 3: TF32 tensor-core batched GEMM + epilogue ----------------
// Per n: C[128 s, 4096 ij] = A[s,d] * B[d,ij],  A = c2^T, B[d, i*64+j] = x[n,d,i,j].
// CTA: 128s x 128ij, K chunked by 16, double-buffered smem, 8-float row skew.
// 8 warps: warp (wr, wc) -> s in [wr*32, wr*32+32), ij in [wc*64, wc*64+64).
// mma.sync.m16n8k8.tf32: warp tile = 2 m-tiles x 8 n-tiles.
#define BKC 16
#define LDAS 136   // row stride: 128 + 8 skew -> conflict-free fragment gathers

__global__ __launch_bounds__(256) void gemm_tf32_kernel(const float* __restrict__ x,
                                                        float* __restrict__ out) {
    __shared__ float As[2][BKC][LDAS];   // A[s,k]: As[k][s]
    __shared__ float Bs[2][BKC][LDAS];   // B[k,ij]: Bs[k][ij]

    int n   = blockIdx.y;
    int bx  = blockIdx.x;          // ij chunk (128 wide)
    int tid = threadIdx.x;
    int w    = tid >> 5, lane = tid & 31;
    int g    = lane >> 2, tig = lane & 3;
    int wr   = w & 3;              // s0  = wr*32
    int wc   = w >> 2;             // ij0 = wc*64

    const float* xb = x + (size_t)(n * D_) * MM_ + bx * 128;

    // cooperative loaders: 512 float4 per tile per stage, 2 per thread
    int r0 = tid >> 5,        c0 = (tid & 31) * 4;   // rows 0..7
    int r1 = (tid + 256) >> 5, c1 = c0;               // rows 8..15

    float4 a0r, a1r, b0r, b1r;

    // preload chunk 0
    a0r = *(const float4*)&g_c2[r0 * S_ + c0];
    a1r = *(const float4*)&g_c2[r1 * S_ + c1];
    b0r = *(const float4*)&xb[(size_t)r0 * MM_ + c0];
    b1r = *(const float4*)&xb[(size_t)r1 * MM_ + c1];

    *(float4*)&As[0][r0][c0] = a0r;
    *(float4*)&As[0][r1][c1] = a1r;
    {
        float4 t0, t1;
        t0.x = tf32r(b0r.x); t0.y = tf32r(b0r.y); t0.z = tf32r(b0r.z); t0.w = tf32r(b0r.w);
        t1.x = tf32r(b1r.x); t1.y = tf32r(b1r.y); t1.z = tf32r(b1r.z); t1.w = tf32r(b1r.w);
        *(float4*)&Bs[0][r0][c0] = t0;
        *(float4*)&Bs[0][r1][c1] = t1;
    }
    __syncthreads();

    float acc[2][8][4];
    #pragma unroll
    for (int mt = 0; mt < 2; mt++)
        #pragma unroll
        for (int nt = 0; nt < 8; nt++)
            #pragma unroll
            for (int v = 0; v < 4; v++) acc[mt][nt][v] = 0.f;

    int buf = 0;
    #pragma unroll 1
    for (int kt = 0; kt < D_ / BKC; kt++) {
        int d0n = (kt + 1) * BKC;
        if (kt + 1 < D_ / BKC) {
            a0r = *(const float4*)&g_c2[(d0n + r0) * S_ + c0];
            a1r = *(const float4*)&g_c2[(d0n + r1) * S_ + c1];
            b0r = *(const float4*)&xb[(size_t)(d0n + r0) * MM_ + c0];
            b1r = *(const float4*)&xb[(size_t)(d0n + r1) * MM_ + c1];
        }

        #pragma unroll
        for (int k0 = 0; k0 < BKC; k0 += 8) {
            uint32_t a[2][4], b[8][2];
            #pragma unroll
            for (int mt = 0; mt < 2; mt++) {
                int sb = wr * 32 + mt * 16;
                a[mt][0] = __float_as_uint(As[buf][k0 + tig    ][sb + g    ]);
                a[mt][1] = __float_as_uint(As[buf][k0 + tig    ][sb + g + 8]);
                a[mt][2] = __float_as_uint(As[buf][k0 + tig + 4][sb + g    ]);
                a[mt][3] = __float_as_uint(As[buf][k0 + tig + 4][sb + g + 8]);
            }
            #pragma unroll
            for (int nt = 0; nt < 8; nt++) {
                int cb = wc * 64 + nt * 8 + g;
                b[nt][0] = __float_as_uint(Bs[buf][k0 + tig    ][cb]);
                b[nt][1] = __float_as_uint(Bs[buf][k0 + tig + 4][cb]);
            }
            #pragma unroll
            for (int mt = 0; mt < 2; mt++)
                #pragma unroll
                for (int nt = 0; nt < 8; nt++) {
                    asm volatile(
                        "mma.sync.aligned.m16n8k8.row.col.f32.tf32.tf32.f32 "
                        "{%0,%1,%2,%3}, {%4,%5,%6,%7}, {%8,%9}, {%0,%1,%2,%3};"
                        : "+f"(acc[mt][nt][0]), "+f"(acc[mt][nt][1]),
                          "+f"(acc[mt][nt][2]), "+f"(acc[mt][nt][3])
                        : "r"(a[mt][0]), "r"(a[mt][1]), "r"(a[mt][2]), "r"(a[mt][3]),
                          "r"(b[nt][0]), "r"(b[nt][1]));
                }
        }

        if (kt + 1 < D_ / BKC) {
            int nb = buf ^ 1;
            *(float4*)&As[nb][r0][c0] = a0r;
            *(float4*)&As[nb][r1][c1] = a1r;
            float4 t0, t1;
            t0.x = tf32r(b0r.x); t0.y = tf32r(b0r.y); t0.z = tf32r(b0r.z); t0.w = tf32r(b0r.w);
            t1.x = tf32r(b1r.x); t1.y = tf32r(b1r.y); t1.z = tf32r(b1r.z); t1.w = tf32r(b1r.w);
            *(float4*)&Bs[nb][r0][c0] = t0;
            *(float4*)&Bs[nb][r1][c1] = t1;
            __syncthreads();
            buf = nb;
        }
    }

    // epilogue: out = acc + P[n,s,i] + P[n,s,j] + Q[n,s]
    // i is uniform per warp: ij_global = bx*128 + wc*64 + (0..63)  ->  i = bx*2 + wc
    int i_row = bx * 2 + wc;
    #pragma unroll
    for (int mt = 0; mt < 2; mt++) {
        #pragma unroll
        for (int half = 0; half < 2; half++) {
            int s = wr * 32 + mt * 16 + g + half * 8;
            const float* Pn = &g_P[(n*S_ + s) * M_];
            float bias_si = Pn[i_row] + g_Q[n*S_ + s];
            size_t obase = (size_t)(n*S_ + s) * MM_ + (size_t)bx * 128 + wc * 64;
            #pragma unroll
            for (int nt = 0; nt < 8; nt++) {
                int j = nt * 8 + 2 * tig;
                float2 r;
                r.x = acc[mt][nt][half*2 + 0] + bias_si + Pn[j];
                r.y = acc[mt][nt][half*2 + 1] + bias_si + Pn[j + 1];
                *(float2*)&out[obase + j] = r;
            }
        }
    }
}

// ---------------- launch ----------------
extern "C" void kernel_launch(void* const* d_in, const int* in_sizes, int n_in,
                              void* d_out, int out_size) {
    const float* x      = (const float*)d_in[0];   // [N,D,M,M]
    const float* coeffs = (const float*)d_in[1];   // [D,S,5]
    const float* bias   = (const float*)d_in[2];   // [1,S,1,1]
    float* out = (float*)d_out;                    // [N,S,M,M]

    prep_coeffs_kernel<<<64, 256>>>(coeffs);
    stats_kernel<<<N_ * D_, 128>>>(x);
    pq_kernel<<<dim3(S_ / 8, N_), 64>>>(bias);
    gemm_tf32_kernel<<<dim3(32, N_), 256>>>(x, out);
}